// round 11
// baseline (speedup 1.0000x reference)
#include <cuda_runtime.h>

#define DDIM  64
#define TLEN  256
#define HID   100
#define G3    300
#define NBLK  128
#define RPB   4
#define NT    640
#define STC   65
#define SROW  (STC*RPB)   // 260
#define HROW  (HID*RPB)   // 400
#define GROW  (G3*RPB)    // 1200

typedef unsigned long long u64;

__device__ __align__(16) float g_states[NBLK * TLEN * SROW];
__device__ __align__(16) float g_hback [NBLK * (TLEN + 1) * HROW];
__device__ __align__(16) float g_gi    [(size_t)NBLK * TLEN * GROW];

struct __align__(16) Smem {
    float sU [HID * G3];    // bgru_U (120000 B)
    float sWb[STC * G3];    // bgru_W ( 78000 B)
    float stGI[2 * GROW];   // sweep gi scratch / per-chain GRU stage (4800 B each)
    float stGH[2 * GROW];   // sweep gh slots   / per-chain decoder scratch
    float hsF[HROW];
    float hsB[HROW];
    float dec4[50 * RPB];
    float bF[2 * G3];
    float bB[2 * G3];
    int   obsC[2][TLEN];    // per-chain private observation mask
};  // ~228 KB

__device__ __forceinline__ float tanha(float x) {
    float y; asm("tanh.approx.f32 %0, %1;" : "=f"(y) : "f"(x)); return y;
}
__device__ __forceinline__ u64 pk2(float w) {
    unsigned wi = __float_as_uint(w);
    u64 r; asm("mov.b64 %0, {%1, %1};" : "=l"(r) : "r"(wi), "r"(wi)); return r;
}
__device__ __forceinline__ void fma2(u64& a, u64 v, u64 w) {
    asm("fma.rn.f32x2 %0, %1, %2, %0;" : "+l"(a) : "l"(v), "l"(w));
}
#define BARC(c) asm volatile("bar.sync %0, %1;" :: "r"((c) + 1), "r"(320) : "memory")

__device__ __forceinline__ float sigg(float x) { return fmaf(0.5f, tanha(0.5f * x), 0.5f); }

// ================== unified backward sweep (all 640 threads, proven R6 form) ==================
__device__ __forceinline__ void sweep_step(Smem* sm, const float* __restrict__ gv,
                                           float* gdict, int tid, int half, int j)
{
    float pgz = 0.f, pgr = 0.f, pgn = 0.f;
    if (tid < HROW) {
        pgz = __ldg(gv + tid); pgr = __ldg(gv + HROW + tid); pgn = __ldg(gv + 2 * HROW + tid);
    }
    if (tid < 600) {
        u64 a01 = half ? 0ull : pk2(sm->bB[G3 + j]), a23 = a01;
        const ulonglong2* hv = reinterpret_cast<const ulonglong2*>(sm->hsB) + half * 50;
        const float* Uc = sm->sU + half * 50 * G3 + j;
#pragma unroll 5
        for (int k = 0; k < 50; k++) {
            u64 u2 = pk2(Uc[k * G3]);
            ulonglong2 h = hv[k];
            fma2(a01, h.x, u2); fma2(a23, h.y, u2);
        }
        reinterpret_cast<ulonglong2*>(sm->stGH)[half * G3 + j] = make_ulonglong2(a01, a23);
    }
    __syncthreads();
    if (tid < HROW) {
        int idx = tid;
        float ghz = sm->stGH[idx]            + sm->stGH[GROW + idx];
        float ghr = sm->stGH[HROW + idx]     + sm->stGH[GROW + HROW + idx];
        float ghn = sm->stGH[2 * HROW + idx] + sm->stGH[GROW + 2 * HROW + idx];
        float z  = sigg(pgz + ghz);
        float rr = sigg(pgr + ghr);
        float n  = tanha(fmaf(rr, ghn, pgn));
        float hnew = fmaf(z, sm->hsB[idx] - n, n);
        sm->hsB[idx] = hnew; gdict[idx] = hnew;
    }
    __syncthreads();
}

// ================== per-chain (320-thread) helpers; 2 batch rows per chain ==================

// forward GRU step: x = state row channels 1..64 (global), weights via __ldg
__device__ __forceinline__ void chain_fwd(Smem* sm, const float* __restrict__ gruW,
                                          const float* __restrict__ gruU,
                                          const float* __restrict__ xg, int c, int ct)
{
    float* stage = sm->stGI + c * GROW;    // 600 u64
    if (ct < G3) {
        int j = ct;
        u64 gi = pk2(sm->bF[j]);
        const float* Wc = gruW + j;
#pragma unroll 4
        for (int k = 0; k < DDIM; k++) {
            u64 x2 = *reinterpret_cast<const u64*>(xg + (k + 1) * 4 + 2 * c);
            fma2(gi, x2, pk2(__ldg(Wc + k * G3)));
        }
        u64 gh = pk2(sm->bF[G3 + j]);
        const float* Uc = gruU + j;
#pragma unroll 5
        for (int k = 0; k < HID; k++) {
            u64 h2 = *reinterpret_cast<const u64*>(sm->hsF + k * 4 + 2 * c);
            fma2(gh, h2, pk2(__ldg(Uc + k * G3)));
        }
        reinterpret_cast<u64*>(stage)[j] = gi;
        reinterpret_cast<u64*>(stage)[G3 + j] = gh;
    }
    BARC(c);
    if (ct < 200) {
        int i = ct >> 1, r = ct & 1;
        const float* sf = stage;
        float giz = sf[i * 2 + r],           gir = sf[(HID + i) * 2 + r],
              gin = sf[(2 * HID + i) * 2 + r];
        float ghz = sf[(G3 + i) * 2 + r],    ghr = sf[(G3 + HID + i) * 2 + r],
              ghn = sf[(G3 + 2 * HID + i) * 2 + r];
        float z  = sigg(giz + ghz);
        float rr = sigg(gir + ghr);
        float n  = tanha(fmaf(rr, ghn, gin));
        int col = i * 4 + 2 * c + r;
        float hnew = fmaf(z, sm->hsF[col] - n, n);
        sm->hsF[col] = hnew;
    }
    BARC(c);
}

// backward GRU step (recompute): h input from hsrc (global dict or sm->hsB), writes hsB + dict
template<bool HASX>
__device__ __forceinline__ void chain_back(Smem* sm, const float* __restrict__ xg,
                                           const float* __restrict__ hsrc,
                                           float* __restrict__ dict, int c, int ct)
{
    float* stage = sm->stGI + c * GROW;
    if (ct < G3) {
        int j = ct;
        u64 gi = pk2(sm->bB[j]);
        if (HASX) {
            const float* Wc = sm->sWb + j;
#pragma unroll 5
            for (int k = 0; k < STC; k++) {
                u64 x2 = *reinterpret_cast<const u64*>(xg + k * 4 + 2 * c);
                fma2(gi, x2, pk2(Wc[k * G3]));
            }
        }
        u64 gh = pk2(sm->bB[G3 + j]);
        const float* Uc = sm->sU + j;
#pragma unroll 5
        for (int k = 0; k < HID; k++) {
            u64 h2 = *reinterpret_cast<const u64*>(hsrc + k * 4 + 2 * c);
            fma2(gh, h2, pk2(Uc[k * G3]));
        }
        reinterpret_cast<u64*>(stage)[j] = gi;
        reinterpret_cast<u64*>(stage)[G3 + j] = gh;
    }
    BARC(c);
    if (ct < 200) {
        int i = ct >> 1, r = ct & 1;
        const float* sf = stage;
        float giz = sf[i * 2 + r],           gir = sf[(HID + i) * 2 + r],
              gin = sf[(2 * HID + i) * 2 + r];
        float ghz = sf[(G3 + i) * 2 + r],    ghr = sf[(G3 + HID + i) * 2 + r],
              ghn = sf[(G3 + 2 * HID + i) * 2 + r];
        float z  = sigg(giz + ghz);
        float rr = sigg(gir + ghr);
        float n  = tanha(fmaf(rr, ghn, gin));
        int col = i * 4 + 2 * c + r;
        float hnew = fmaf(z, hsrc[col] - n, n);
        sm->hsB[col] = hnew;
        dict[col] = hnew;
    }
    BARC(c);
}

// decoder event for one chain (2 rows)
__device__ __forceinline__ void chain_decoder(int lvl,
                                              const float* __restrict__ decW,
                                              const float* __restrict__ decB,
                                              const float* __restrict__ meanW,
                                              const float* __restrict__ meanB,
                                              Smem* sm, const float* __restrict__ hbg,
                                              float* __restrict__ gout, int c, int ct)
{
    float* scr = sm->stGH + c * GROW;     // 4800 B scratch
    if (ct < 250) {                       // [2,200]@[200,50], 5 k-groups of 40
        int j = ct % 50, kg = ct / 50;
        u64 a = 0;
        const float* Wl = decW + lvl * 200 * 50;
        int kbeg = kg * 40;
#pragma unroll 5
        for (int kk = 0; kk < 40; kk++) {
            int k = kbeg + kk;
            u64 h2 = (k < HID)
                ? *reinterpret_cast<const u64*>(sm->hsF + k * 4 + 2 * c)
                : *reinterpret_cast<const u64*>(hbg + (k - HID) * 4 + 2 * c);
            fma2(a, h2, pk2(__ldg(&Wl[k * 50 + j])));
        }
        reinterpret_cast<u64*>(scr)[ct] = a;
    }
    BARC(c);
    if (ct < 50) {
        float b = __ldg(&decB[lvl * 50 + ct]);
        float s0 = b, s1 = b;
#pragma unroll
        for (int g = 0; g < 5; g++) {
            s0 += scr[(g * 50 + ct) * 2 + 0];
            s1 += scr[(g * 50 + ct) * 2 + 1];
        }
        sm->dec4[ct * 4 + 2 * c + 0] = fmaxf(s0, 0.f);
        sm->dec4[ct * 4 + 2 * c + 1] = fmaxf(s1, 0.f);
    }
    BARC(c);
    {                                     // [2,50]@[50,64], 5 k-groups of 10
        int j = ct & 63, kg = ct >> 6;
        u64 m = 0;
        const float* Ml = meanW + lvl * 50 * DDIM;
        int kbeg = kg * 10;
#pragma unroll
        for (int kk = 0; kk < 10; kk++) {
            int k = kbeg + kk;
            u64 d2 = *reinterpret_cast<const u64*>(sm->dec4 + k * 4 + 2 * c);
            fma2(m, d2, pk2(__ldg(&Ml[k * DDIM + j])));
        }
        reinterpret_cast<u64*>(scr)[ct] = m;
    }
    BARC(c);
    if (ct < DDIM) {
        float b = __ldg(&meanB[lvl * DDIM + ct]);
        float s0 = b, s1 = b;
#pragma unroll
        for (int g = 0; g < 5; g++) {
            s0 += scr[(g * DDIM + ct) * 2 + 0];
            s1 += scr[(g * DDIM + ct) * 2 + 1];
        }
        gout[ct * 4 + 2 * c + 0] = s0;
        gout[ct * 4 + 2 * c + 1] = s1;
    }
    if (ct >= DDIM && ct < DDIM + 2) gout[DDIM * 4 + 2 * c + (ct - DDIM)] = 1.0f;
    BARC(c);
}

__global__ void __launch_bounds__(NT, 1)
naomi_kernel(const float* __restrict__ a,
             const float* __restrict__ gruW,  const float* __restrict__ gruU,
             const float* __restrict__ gruB,
             const float* __restrict__ bgruW, const float* __restrict__ bgruU,
             const float* __restrict__ bgruB,
             const float* __restrict__ decW,  const float* __restrict__ decB,
             const float* __restrict__ meanW, const float* __restrict__ meanB,
             float* __restrict__ out)
{
    extern __shared__ __align__(16) char smraw[];
    Smem* sm = reinterpret_cast<Smem*>(smraw);
    const int tid = threadIdx.x;
    const int bid = blockIdx.x;
    const int half = (tid < 600) ? (tid >= 300) : 0;
    const int j    = (tid < 600) ? (tid - half * 300) : 0;

    for (int i = tid; i < HID * G3; i += NT) sm->sU[i]  = bgruU[i];
    for (int i = tid; i < STC * G3; i += NT) sm->sWb[i] = bgruW[i];
    for (int i = tid; i < 2 * G3;   i += NT) { sm->bF[i] = gruB[i]; sm->bB[i] = bgruB[i]; }

    for (int t = tid; t < TLEN; t += NT) {
        int o = (a[t * 3 + 2] > 0.5f) ? 1 : 0;
        sm->obsC[0][t] = o; sm->obsC[1][t] = o;
    }

    float* gst = g_states + bid * TLEN * SROW;
    float* ghb = g_hback  + bid * (TLEN + 1) * HROW;
    float* ggi = g_gi     + (size_t)bid * TLEN * GROW;
    const int b0row = bid * RPB;
    for (int idx = tid; idx < RPB * STC * TLEN; idx += NT) {
        int t = idx & (TLEN - 1);
        int tmp = idx >> 8;
        int k = tmp % STC, r = tmp / STC;
        int b = b0row + r;
        float v = (k < DDIM) ? a[((b * DDIM + k) * TLEN + t) * 3]
                             : a[((b * DDIM) * TLEN + t) * 3 + 2];
        gst[t * SROW + k * RPB + r] = v;
    }
    for (int i = tid; i < HROW; i += NT) {
        sm->hsB[i] = 0.f; sm->hsF[i] = 0.f; ghb[TLEN * HROW + i] = 0.f;
    }
    __syncthreads();

    // ---- parallel prepass: gi[t] = states[t] @ bgru_W + b0, t = 1..255 ----
    for (int task = tid; task < (TLEN - 1) * G3; task += NT) {
        int t = task / G3 + 1;
        int jj = task - (t - 1) * G3;
        u64 a01 = pk2(sm->bB[jj]), a23 = a01;
        const ulonglong2* xv = reinterpret_cast<const ulonglong2*>(gst + t * SROW);
#pragma unroll 5
        for (int k = 0; k < STC; k++) {
            u64 w2 = pk2(sm->sWb[k * G3 + jj]);
            ulonglong2 x = xv[k];
            fma2(a01, x.x, w2); fma2(a23, x.y, w2);
        }
        reinterpret_cast<ulonglong2*>(ggi)[(size_t)t * G3 + jj] = make_ulonglong2(a01, a23);
    }
    __syncthreads();

    // ---- phase 1: unified backward sweep ----
    for (int t = TLEN - 1; t >= 1; t--)
        sweep_step(sm, ggi + (size_t)t * GROW, ghb + t * HROW, tid, half, j);

    // ---- phase 2: forked forward interpolation (two independent 2-row chains) ----
    {
        const int c  = (tid >= 320) ? 1 : 0;
        const int ct = tid - c * 320;
        int* obs = sm->obsC[c];

        chain_fwd(sm, gruW, gruU, gst, c, ct);

        int curr_p = 0;
        while (curr_p < TLEN - 1) {
            if (obs[curr_p + 1]) {
                curr_p++;
                chain_fwd(sm, gruW, gruU, gst + curr_p * SROW, c, ct);
            } else {
                int next_p = curr_p + 1;
                while (next_p < TLEN && !obs[next_p]) next_p++;
                int step = 1;
                while (curr_p + 2 * step <= next_p && step <= 8) step <<= 1;
                if (step > 1) step >>= 1;
                int lvl = (step == 8) ? 3 : (step == 4) ? 2 : (step == 2) ? 1 : 0;

                chain_decoder(lvl, decW, decB, meanW, meanB, sm,
                              ghb + (curr_p + 2 * step) * HROW,
                              gst + (curr_p + step) * SROW, c, ct);

                if (step > 1) {
                    int right = curr_p + step, left = curr_p + (step >> 1);
                    chain_back<true>(sm, gst + right * SROW, ghb + (right + 1) * HROW,
                                     ghb + right * HROW, c, ct);
                    for (int i2 = right - 1; i2 >= left; i2--)
                        chain_back<false>(sm, nullptr, sm->hsB, ghb + i2 * HROW, c, ct);
                }
                obs[curr_p + step] = 1;
            }
        }
    }
    __syncthreads();

    // ---- output: out[b][d][t] = states[t][b][d+1] ----
    for (int idx = tid; idx < RPB * DDIM * TLEN; idx += NT) {
        int t = idx & (TLEN - 1);
        int tmp = idx >> 8;
        int d = tmp % DDIM, r = tmp / DDIM;
        int b = b0row + r;
        out[(b * DDIM + d) * TLEN + t] = gst[t * SROW + (d + 1) * RPB + r];
    }
}

extern "C" void kernel_launch(void* const* d_in, const int* in_sizes, int n_in,
                              void* d_out, int out_size)
{
    const float* a     = (const float*)d_in[0];
    const float* gruW  = (const float*)d_in[1];
    const float* gruU  = (const float*)d_in[2];
    const float* gruB  = (const float*)d_in[3];
    const float* bgruW = (const float*)d_in[4];
    const float* bgruU = (const float*)d_in[5];
    const float* bgruB = (const float*)d_in[6];
    const float* decW  = (const float*)d_in[7];
    const float* decB  = (const float*)d_in[8];
    const float* meanW = (const float*)d_in[9];
    const float* meanB = (const float*)d_in[10];
    float* out = (float*)d_out;

    static int smem_set = 0;
    if (!smem_set) {
        cudaFuncSetAttribute(naomi_kernel, cudaFuncAttributeMaxDynamicSharedMemorySize,
                             (int)sizeof(Smem));
        smem_set = 1;
    }
    naomi_kernel<<<NBLK, NT, sizeof(Smem)>>>(a, gruW, gruU, gruB, bgruW, bgruU, bgruB,
                                             decW, decB, meanW, meanB, out);
}

// round 13
// speedup vs baseline: 1.4790x; 1.4790x over previous
#include <cuda_runtime.h>

#define DDIM  64
#define TLEN  256
#define HID   100
#define G3    300
#define NBLK  128
#define RPB   4
#define NT    640
#define STC   65
#define SROW  (STC*RPB)   // 260
#define HROW  (HID*RPB)   // 400
#define GROW  (G3*RPB)    // 1200

typedef unsigned long long u64;

__device__ __align__(16) float g_states[NBLK * TLEN * SROW];
__device__ __align__(16) float g_hback [NBLK * (TLEN + 1) * HROW];
__device__ __align__(16) float g_gi    [(size_t)NBLK * TLEN * GROW];

struct __align__(16) Smem {
    float sU [HID * G3];    // bgru_U (120000 B)
    float sWx[STC * G3];    // bgru_W during prepass; gruW (64*300) after swap
    float stGI[2 * GROW];   // gi partials, halves   (9600 B)
    float stGH[2 * GROW];   // gh partials, halves   (9600 B)
    float hsF[HROW];
    float hsB[HROW];
    float dec4[50 * RPB];
    float bF[2 * G3];
    float bB[2 * G3];
    int   obs[TLEN];
};  // ~227 KB

__device__ __forceinline__ float tanha(float x) {
    float y; asm("tanh.approx.f32 %0, %1;" : "=f"(y) : "f"(x)); return y;
}
__device__ __forceinline__ u64 pk2(float w) {
    unsigned wi = __float_as_uint(w);
    u64 r; asm("mov.b64 %0, {%1, %1};" : "=l"(r) : "r"(wi), "r"(wi)); return r;
}
__device__ __forceinline__ void fma2(u64& a, u64 v, u64 w) {
    asm("fma.rn.f32x2 %0, %1, %2, %0;" : "+l"(a) : "l"(v), "l"(w));
}
__device__ __forceinline__ void add2(u64& a, u64 b) {
    asm("add.rn.f32x2 %0, %0, %1;" : "+l"(a) : "l"(b));
}
__device__ __forceinline__ float sigg(float x) { return fmaf(0.5f, tanha(0.5f * x), 0.5f); }

// 50-iter smem matvec as 2x25 interleaved chains (4 accumulators)
__device__ __forceinline__ void mv_sm50(const float* __restrict__ Wcol, const float* hv_,
                                        int kb, u64& a01, u64& a23)
{
    const ulonglong2* hv = reinterpret_cast<const ulonglong2*>(hv_) + kb;
    const float* Wc = Wcol + kb * G3;
    u64 b01 = 0, b23 = 0;
#pragma unroll 5
    for (int k = 0; k < 25; k++) {
        u64 wa = pk2(Wc[k * G3]);
        u64 wb = pk2(Wc[(k + 25) * G3]);
        ulonglong2 ha = hv[k], hb = hv[k + 25];
        fma2(a01, ha.x, wa); fma2(a23, ha.y, wa);
        fma2(b01, hb.x, wb); fma2(b23, hb.y, wb);
    }
    add2(a01, b01); add2(a23, b23);
}
// 50-iter global-weight matvec, 2x25 interleaved (__ldg, L2-hot)
__device__ __forceinline__ void mv_gl50(const float* __restrict__ Wcol, const float* hv_,
                                        int kb, u64& a01, u64& a23)
{
    const ulonglong2* hv = reinterpret_cast<const ulonglong2*>(hv_) + kb;
    const float* Wc = Wcol + kb * G3;
    u64 b01 = 0, b23 = 0;
#pragma unroll 5
    for (int k = 0; k < 25; k++) {
        u64 wa = pk2(__ldg(Wc + k * G3));
        u64 wb = pk2(__ldg(Wc + (k + 25) * G3));
        ulonglong2 ha = hv[k], hb = hv[k + 25];
        fma2(a01, ha.x, wa); fma2(a23, ha.y, wa);
        fma2(b01, hb.x, wb); fma2(b23, hb.y, wb);
    }
    add2(a01, b01); add2(a23, b23);
}

// ---- sweep step: gi precomputed in g_gi (prefetched), gh split 2x(2x25) ----
__device__ __forceinline__ void sweep_step(Smem* sm, const float* __restrict__ gv,
                                           float* gdict, int tid, int half, int j)
{
    float pgz = 0.f, pgr = 0.f, pgn = 0.f;
    if (tid < HROW) {
        pgz = __ldg(gv + tid); pgr = __ldg(gv + HROW + tid); pgn = __ldg(gv + 2 * HROW + tid);
    }
    if (tid < 600) {
        u64 a01 = half ? 0ull : pk2(sm->bB[G3 + j]), a23 = a01;
        mv_sm50(sm->sU + j, sm->hsB, half * 50, a01, a23);
        reinterpret_cast<ulonglong2*>(sm->stGH)[half * G3 + j] = make_ulonglong2(a01, a23);
    }
    __syncthreads();
    if (tid < HROW) {
        int idx = tid;
        float ghz = sm->stGH[idx]            + sm->stGH[GROW + idx];
        float ghr = sm->stGH[HROW + idx]     + sm->stGH[GROW + HROW + idx];
        float ghn = sm->stGH[2 * HROW + idx] + sm->stGH[GROW + 2 * HROW + idx];
        float z  = sigg(pgz + ghz);
        float rr = sigg(pgr + ghr);
        float n  = tanha(fmaf(rr, ghn, pgn));
        float hnew = fmaf(z, sm->hsB[idx] - n, n);
        sm->hsB[idx] = hnew; gdict[idx] = hnew;
    }
    __syncthreads();
}

// ---- backward GRU step (recompute): x-weights via __ldg(bgruW), gh from smem sU ----
template<bool HASX>
__device__ __forceinline__ void back_step(Smem* sm, const float* __restrict__ bgruW,
                                          const float* __restrict__ xg, const float* hsrc,
                                          float* gdict, int tid, int half, int j)
{
    if (tid < 600) {
        if (HASX) {
            int kb = half ? 33 : 0, kn = half ? 32 : 33;
            u64 gi01 = half ? 0ull : pk2(sm->bB[j]);
            u64 gi23 = gi01;
            const ulonglong2* xv = reinterpret_cast<const ulonglong2*>(xg) + kb;
            const float* Wc = bgruW + kb * G3 + j;
#pragma unroll 3
            for (int k = 0; k < kn; k++) {
                u64 w2 = pk2(__ldg(Wc + k * G3));
                ulonglong2 x = xv[k];
                fma2(gi01, x.x, w2); fma2(gi23, x.y, w2);
            }
            reinterpret_cast<ulonglong2*>(sm->stGI)[half * G3 + j] = make_ulonglong2(gi01, gi23);
        }
        u64 gh01 = half ? 0ull : pk2(sm->bB[G3 + j]);
        u64 gh23 = gh01;
        mv_sm50(sm->sU + j, hsrc, half * 50, gh01, gh23);
        reinterpret_cast<ulonglong2*>(sm->stGH)[half * G3 + j] = make_ulonglong2(gh01, gh23);
    }
    __syncthreads();
    if (tid < HROW) {
        int idx = tid;
        float giz, gir, gin;
        if (HASX) {
            giz = sm->stGI[idx]            + sm->stGI[GROW + idx];
            gir = sm->stGI[HROW + idx]     + sm->stGI[GROW + HROW + idx];
            gin = sm->stGI[2 * HROW + idx] + sm->stGI[GROW + 2 * HROW + idx];
        } else {
            int i = idx >> 2;
            giz = sm->bB[i]; gir = sm->bB[HID + i]; gin = sm->bB[2 * HID + i];
        }
        float ghz = sm->stGH[idx]            + sm->stGH[GROW + idx];
        float ghr = sm->stGH[HROW + idx]     + sm->stGH[GROW + HROW + idx];
        float ghn = sm->stGH[2 * HROW + idx] + sm->stGH[GROW + 2 * HROW + idx];
        float z  = sigg(giz + ghz);
        float rr = sigg(gir + ghr);
        float n  = tanha(fmaf(rr, ghn, gin));
        float hnew = fmaf(z, hsrc[idx] - n, n);
        sm->hsB[idx] = hnew;
        if (gdict) gdict[idx] = hnew;
    }
    __syncthreads();
}

// ---- forward GRU step: gi weights from smem (sWx holds gruW), gh via __ldg(gruU) ----
__device__ __forceinline__ void fwd_step(const float* __restrict__ gruU,
                                         Smem* sm, const float* xg, int tid, int half, int j)
{
    if (tid < 600) {
        // gi: 32 iters as 2x16 interleaved, weights in smem
        u64 gi01 = half ? 0ull : pk2(sm->bF[j]);
        u64 gi23 = gi01;
        {
            u64 c01 = 0, c23 = 0;
            const ulonglong2* xv = reinterpret_cast<const ulonglong2*>(xg) + 1 + half * 32;
            const float* Wc = sm->sWx + half * 32 * G3 + j;
#pragma unroll 4
            for (int k = 0; k < 16; k++) {
                u64 wa = pk2(Wc[k * G3]);
                u64 wb = pk2(Wc[(k + 16) * G3]);
                ulonglong2 xa = xv[k], xb = xv[k + 16];
                fma2(gi01, xa.x, wa); fma2(gi23, xa.y, wa);
                fma2(c01, xb.x, wb);  fma2(c23, xb.y, wb);
            }
            add2(gi01, c01); add2(gi23, c23);
        }
        // gh: 50 iters as 2x25, weights via L2
        u64 gh01 = half ? 0ull : pk2(sm->bF[G3 + j]);
        u64 gh23 = gh01;
        mv_gl50(gruU + j, sm->hsF, half * 50, gh01, gh23);
        reinterpret_cast<ulonglong2*>(sm->stGI)[half * G3 + j] = make_ulonglong2(gi01, gi23);
        reinterpret_cast<ulonglong2*>(sm->stGH)[half * G3 + j] = make_ulonglong2(gh01, gh23);
    }
    __syncthreads();
    if (tid < HROW) {
        int idx = tid;
        float giz = sm->stGI[idx]            + sm->stGI[GROW + idx];
        float gir = sm->stGI[HROW + idx]     + sm->stGI[GROW + HROW + idx];
        float gin = sm->stGI[2 * HROW + idx] + sm->stGI[GROW + 2 * HROW + idx];
        float ghz = sm->stGH[idx]            + sm->stGH[GROW + idx];
        float ghr = sm->stGH[HROW + idx]     + sm->stGH[GROW + HROW + idx];
        float ghn = sm->stGH[2 * HROW + idx] + sm->stGH[GROW + 2 * HROW + idx];
        float z  = sigg(giz + ghz);
        float rr = sigg(gir + ghr);
        float n  = tanha(fmaf(rr, ghn, gin));
        float hnew = fmaf(z, sm->hsF[idx] - n, n);
        sm->hsF[idx] = hnew;
    }
    __syncthreads();
}

// ---- decoder event (R6 form) ----
__device__ __forceinline__ void decoder_event(int lvl,
                                              const float* __restrict__ decW,
                                              const float* __restrict__ decB,
                                              const float* __restrict__ meanW,
                                              const float* __restrict__ meanB,
                                              Smem* sm, const float* hbg,
                                              float* gout, int tid)
{
    float* stage = sm->stGI;
    if (tid < 500) {                  // [4,200]@[200,50], k in 10 groups of 20
        int j = tid % 50, kg = tid / 50;
        u64 a01 = 0, a23 = 0;
        const float* Wl = decW + lvl * 200 * 50;
        int kbeg = kg * 20;
#pragma unroll 5
        for (int kk = 0; kk < 20; kk++) {
            int k = kbeg + kk;
            const float* src = (k < HID) ? (sm->hsF + k * RPB) : (hbg + (k - HID) * RPB);
            ulonglong2 h = *reinterpret_cast<const ulonglong2*>(src);
            u64 w2 = pk2(__ldg(&Wl[k * 50 + j]));
            fma2(a01, h.x, w2); fma2(a23, h.y, w2);
        }
        reinterpret_cast<ulonglong2*>(stage)[tid] = make_ulonglong2(a01, a23);
    }
    __syncthreads();
    if (tid < 50) {
        float b = __ldg(&decB[lvl * 50 + tid]);
        float s0 = b, s1 = b, s2 = b, s3 = b;
#pragma unroll
        for (int g = 0; g < 10; g++) {
            int base = (g * 50 + tid) * 4;
            s0 += stage[base]; s1 += stage[base + 1]; s2 += stage[base + 2]; s3 += stage[base + 3];
        }
        sm->dec4[tid * 4 + 0] = fmaxf(s0, 0.f); sm->dec4[tid * 4 + 1] = fmaxf(s1, 0.f);
        sm->dec4[tid * 4 + 2] = fmaxf(s2, 0.f); sm->dec4[tid * 4 + 3] = fmaxf(s3, 0.f);
    }
    __syncthreads();
    {                                 // [4,50]@[50,64], k in 10 groups of 5
        int j = tid & 63, kg = tid >> 6;
        u64 m01 = 0, m23 = 0;
        const float* Ml = meanW + lvl * 50 * DDIM;
        int kbeg = kg * 5;
#pragma unroll
        for (int kk = 0; kk < 5; kk++) {
            int k = kbeg + kk;
            ulonglong2 d = reinterpret_cast<const ulonglong2*>(sm->dec4)[k];
            u64 w2 = pk2(__ldg(&Ml[k * DDIM + j]));
            fma2(m01, d.x, w2); fma2(m23, d.y, w2);
        }
        reinterpret_cast<ulonglong2*>(stage)[tid] = make_ulonglong2(m01, m23);
    }
    __syncthreads();
    if (tid < DDIM) {
        float b = __ldg(&meanB[lvl * DDIM + tid]);
        float s0 = b, s1 = b, s2 = b, s3 = b;
#pragma unroll
        for (int g = 0; g < 10; g++) {
            int base = (g * DDIM + tid) * 4;
            s0 += stage[base]; s1 += stage[base + 1]; s2 += stage[base + 2]; s3 += stage[base + 3];
        }
        gout[tid * RPB + 0] = s0; gout[tid * RPB + 1] = s1;
        gout[tid * RPB + 2] = s2; gout[tid * RPB + 3] = s3;
    }
    if (tid >= DDIM && tid < DDIM + RPB) gout[DDIM * RPB + (tid - DDIM)] = 1.0f;
    __syncthreads();
}

__global__ void __launch_bounds__(NT, 1)
naomi_kernel(const float* __restrict__ a,
             const float* __restrict__ gruW,  const float* __restrict__ gruU,
             const float* __restrict__ gruB,
             const float* __restrict__ bgruW, const float* __restrict__ bgruU,
             const float* __restrict__ bgruB,
             const float* __restrict__ decW,  const float* __restrict__ decB,
             const float* __restrict__ meanW, const float* __restrict__ meanB,
             float* __restrict__ out)
{
    extern __shared__ __align__(16) char smraw[];
    Smem* sm = reinterpret_cast<Smem*>(smraw);
    const int tid = threadIdx.x;
    const int bid = blockIdx.x;
    const int half = (tid < 600) ? (tid >= 300) : 0;
    const int j    = (tid < 600) ? (tid - half * 300) : 0;

    for (int i = tid; i < HID * G3; i += NT) sm->sU[i]  = bgruU[i];
    for (int i = tid; i < STC * G3; i += NT) sm->sWx[i] = bgruW[i];
    for (int i = tid; i < 2 * G3;   i += NT) { sm->bF[i] = gruB[i]; sm->bB[i] = bgruB[i]; }

    for (int t = tid; t < TLEN; t += NT) sm->obs[t] = (a[t * 3 + 2] > 0.5f) ? 1 : 0;

    float* gst = g_states + bid * TLEN * SROW;
    float* ghb = g_hback  + bid * (TLEN + 1) * HROW;
    float* ggi = g_gi     + (size_t)bid * TLEN * GROW;
    const int b0row = bid * RPB;
    for (int idx = tid; idx < RPB * STC * TLEN; idx += NT) {
        int t = idx & (TLEN - 1);
        int tmp = idx >> 8;
        int k = tmp % STC, r = tmp / STC;
        int b = b0row + r;
        float v = (k < DDIM) ? a[((b * DDIM + k) * TLEN + t) * 3]
                             : a[((b * DDIM) * TLEN + t) * 3 + 2];
        gst[t * SROW + k * RPB + r] = v;
    }
    for (int i = tid; i < HROW; i += NT) {
        sm->hsB[i] = 0.f; sm->hsF[i] = 0.f; ghb[TLEN * HROW + i] = 0.f;
    }
    __syncthreads();

    // ---- parallel prepass: gi[t] = states[t] @ bgru_W + b0, t = 1..255 (sWx = bgru_W) ----
    for (int task = tid; task < (TLEN - 1) * G3; task += NT) {
        int t = task / G3 + 1;
        int jj = task - (t - 1) * G3;
        u64 a01 = pk2(sm->bB[jj]), a23 = a01;
        const ulonglong2* xv = reinterpret_cast<const ulonglong2*>(gst + t * SROW);
#pragma unroll 5
        for (int k = 0; k < STC; k++) {
            u64 w2 = pk2(sm->sWx[k * G3 + jj]);
            ulonglong2 x = xv[k];
            fma2(a01, x.x, w2); fma2(a23, x.y, w2);
        }
        reinterpret_cast<ulonglong2*>(ggi)[(size_t)t * G3 + jj] = make_ulonglong2(a01, a23);
    }
    __syncthreads();

    // ---- swap: sWx region now holds gruW (fwd gi weights, used 256x in interp) ----
    for (int i = tid; i < DDIM * G3; i += NT) sm->sWx[i] = gruW[i];
    __syncthreads();

    // ---- phase 1: backward sweep ----
    for (int t = TLEN - 1; t >= 1; t--)
        sweep_step(sm, ggi + (size_t)t * GROW, ghb + t * HROW, tid, half, j);

    // ---- phase 2: forward interpolation ----
    fwd_step(gruU, sm, gst, tid, half, j);

    int curr_p = 0;
    while (curr_p < TLEN - 1) {
        if (sm->obs[curr_p + 1]) {
            curr_p++;
            fwd_step(gruU, sm, gst + curr_p * SROW, tid, half, j);
        } else {
            int next_p = curr_p + 1;
            while (next_p < TLEN && !sm->obs[next_p]) next_p++;
            int step = 1;
            while (curr_p + 2 * step <= next_p && step <= 8) step <<= 1;
            if (step > 1) step >>= 1;
            int lvl = (step == 8) ? 3 : (step == 4) ? 2 : (step == 2) ? 1 : 0;

            decoder_event(lvl, decW, decB, meanW, meanB, sm,
                          ghb + (curr_p + 2 * step) * HROW,
                          gst + (curr_p + step) * SROW, tid);

            if (step > 1) {
                int right = curr_p + step, left = curr_p + (step >> 1);
                back_step<true>(sm, bgruW, gst + right * SROW, ghb + (right + 1) * HROW,
                                ghb + right * HROW, tid, half, j);
                for (int i2 = right - 1; i2 >= left; i2--)
                    back_step<false>(sm, bgruW, nullptr, sm->hsB, ghb + i2 * HROW,
                                     tid, half, j);
            }
            sm->obs[curr_p + step] = 1;
            __syncthreads();
        }
    }

    // ---- output: out[b][d][t] = states[t][b][d+1] ----
    __syncthreads();
    for (int idx = tid; idx < RPB * DDIM * TLEN; idx += NT) {
        int t = idx & (TLEN - 1);
        int tmp = idx >> 8;
        int d = tmp % DDIM, r = tmp / DDIM;
        int b = b0row + r;
        out[(b * DDIM + d) * TLEN + t] = gst[t * SROW + (d + 1) * RPB + r];
    }
}

extern "C" void kernel_launch(void* const* d_in, const int* in_sizes, int n_in,
                              void* d_out, int out_size)
{
    const float* a     = (const float*)d_in[0];
    const float* gruW  = (const float*)d_in[1];
    const float* gruU  = (const float*)d_in[2];
    const float* gruB  = (const float*)d_in[3];
    const float* bgruW = (const float*)d_in[4];
    const float* bgruU = (const float*)d_in[5];
    const float* bgruB = (const float*)d_in[6];
    const float* decW  = (const float*)d_in[7];
    const float* decB  = (const float*)d_in[8];
    const float* meanW = (const float*)d_in[9];
    const float* meanB = (const float*)d_in[10];
    float* out = (float*)d_out;

    static int smem_set = 0;
    if (!smem_set) {
        cudaFuncSetAttribute(naomi_kernel, cudaFuncAttributeMaxDynamicSharedMemorySize,
                             (int)sizeof(Smem));
        smem_set = 1;
    }
    naomi_kernel<<<NBLK, NT, sizeof(Smem)>>>(a, gruW, gruU, gruB, bgruW, bgruU, bgruB,
                                             decW, decB, meanW, meanB, out);
}

// round 14
// speedup vs baseline: 1.4999x; 1.0142x over previous
#include <cuda_runtime.h>

#define DDIM  64
#define TLEN  256
#define HID   100
#define G3    300
#define NBLK  128
#define RPB   4
#define NT    640
#define STC   65
#define SROW  (STC*RPB)   // 260
#define HROW  (HID*RPB)   // 400
#define GROW  (G3*RPB)    // 1200

typedef unsigned long long u64;

__device__ __align__(16) float g_states[NBLK * TLEN * SROW];
__device__ __align__(16) float g_hback [NBLK * (TLEN + 1) * HROW];
__device__ __align__(16) float g_gi    [(size_t)NBLK * TLEN * GROW];

struct __align__(16) Smem {
    float sU [HID * G3];    // bgru_U (120000 B)
    float sWx[STC * G3];    // bgru_W during prepass; gruW after swap
    float stGI[2 * GROW];   // gi partials, halves   (9600 B)
    float stGH[2 * GROW];   // gh partials, halves   (9600 B)
    float hsF[HROW];
    float hsB[HROW];
    float dec4[50 * RPB];
    float bF[2 * G3];
    float bB[2 * G3];
    int   obs[TLEN];
};  // ~227 KB

__device__ __forceinline__ float tanha(float x) {
    float y; asm("tanh.approx.f32 %0, %1;" : "=f"(y) : "f"(x)); return y;
}
__device__ __forceinline__ u64 pk2(float w) {
    unsigned wi = __float_as_uint(w);
    u64 r; asm("mov.b64 %0, {%1, %1};" : "=l"(r) : "r"(wi), "r"(wi)); return r;
}
__device__ __forceinline__ void fma2(u64& a, u64 v, u64 w) {
    asm("fma.rn.f32x2 %0, %1, %2, %0;" : "+l"(a) : "l"(v), "l"(w));
}
__device__ __forceinline__ void add2(u64& a, u64 b) {
    asm("add.rn.f32x2 %0, %0, %1;" : "+l"(a) : "l"(b));
}
__device__ __forceinline__ float sigg(float x) { return fmaf(0.5f, tanha(0.5f * x), 0.5f); }

// 50-iter smem matvec, fully unrolled, 2x25 interleaved chains (4 accumulators)
__device__ __forceinline__ void mv_sm50(const float* __restrict__ Wcol, const float* hv_,
                                        int kb, u64& a01, u64& a23)
{
    const ulonglong2* hv = reinterpret_cast<const ulonglong2*>(hv_) + kb;
    const float* Wc = Wcol + kb * G3;
    u64 b01 = 0, b23 = 0;
#pragma unroll
    for (int k = 0; k < 25; k++) {
        u64 wa = pk2(Wc[k * G3]);
        u64 wb = pk2(Wc[(k + 25) * G3]);
        ulonglong2 ha = hv[k], hb = hv[k + 25];
        fma2(a01, ha.x, wa); fma2(a23, ha.y, wa);
        fma2(b01, hb.x, wb); fma2(b23, hb.y, wb);
    }
    add2(a01, b01); add2(a23, b23);
}

// 50-iter global-weight matvec: explicit 25-wide weight preload (MLP=25) then FMA burst.
// Weight addresses are h-independent, so the L2 latency is paid once per chunk.
__device__ __forceinline__ void mv_gl50(const float* __restrict__ Wcol, const float* hv_,
                                        int kb, u64& a01, u64& a23)
{
    const ulonglong2* hv = reinterpret_cast<const ulonglong2*>(hv_) + kb;
    const float* Wc = Wcol + kb * G3;
    u64 b01 = 0, b23 = 0;
    float w[25];
#pragma unroll
    for (int k = 0; k < 25; k++) w[k] = __ldg(Wc + k * G3);
#pragma unroll
    for (int k = 0; k < 25; k++) {
        ulonglong2 h = hv[k];
        u64 w2 = pk2(w[k]);
        if (k & 1) { fma2(b01, h.x, w2); fma2(b23, h.y, w2); }
        else       { fma2(a01, h.x, w2); fma2(a23, h.y, w2); }
    }
#pragma unroll
    for (int k = 0; k < 25; k++) w[k] = __ldg(Wc + (k + 25) * G3);
#pragma unroll
    for (int k = 0; k < 25; k++) {
        ulonglong2 h = hv[k + 25];
        u64 w2 = pk2(w[k]);
        if (k & 1) { fma2(b01, h.x, w2); fma2(b23, h.y, w2); }
        else       { fma2(a01, h.x, w2); fma2(a23, h.y, w2); }
    }
    add2(a01, b01); add2(a23, b23);
}

// ---- sweep step: gi precomputed in g_gi (prefetched), gh split 2x(2x25) ----
__device__ __forceinline__ void sweep_step(Smem* sm, const float* __restrict__ gv,
                                           float* gdict, int tid, int half, int j)
{
    float pgz = 0.f, pgr = 0.f, pgn = 0.f;
    if (tid < HROW) {
        pgz = __ldg(gv + tid); pgr = __ldg(gv + HROW + tid); pgn = __ldg(gv + 2 * HROW + tid);
    }
    if (tid < 600) {
        u64 a01 = half ? 0ull : pk2(sm->bB[G3 + j]), a23 = a01;
        mv_sm50(sm->sU + j, sm->hsB, half * 50, a01, a23);
        reinterpret_cast<ulonglong2*>(sm->stGH)[half * G3 + j] = make_ulonglong2(a01, a23);
    }
    __syncthreads();
    if (tid < HROW) {
        int idx = tid;
        float ghz = sm->stGH[idx]            + sm->stGH[GROW + idx];
        float ghr = sm->stGH[HROW + idx]     + sm->stGH[GROW + HROW + idx];
        float ghn = sm->stGH[2 * HROW + idx] + sm->stGH[GROW + 2 * HROW + idx];
        float z  = sigg(pgz + ghz);
        float rr = sigg(pgr + ghr);
        float n  = tanha(fmaf(rr, ghn, pgn));
        float hnew = fmaf(z, sm->hsB[idx] - n, n);
        sm->hsB[idx] = hnew; gdict[idx] = hnew;
    }
    __syncthreads();
}

// ---- backward GRU step (recompute): x-weights via __ldg(bgruW), gh from smem sU ----
template<bool HASX>
__device__ __forceinline__ void back_step(Smem* sm, const float* __restrict__ bgruW,
                                          const float* __restrict__ xg, const float* hsrc,
                                          float* gdict, int tid, int half, int j)
{
    if (tid < 600) {
        if (HASX) {
            int kb = half ? 33 : 0;
            const int kn = half ? 32 : 33;
            u64 gi01 = half ? 0ull : pk2(sm->bB[j]);
            u64 gi23 = gi01;
            const ulonglong2* xv = reinterpret_cast<const ulonglong2*>(xg) + kb;
            const float* Wc = bgruW + kb * G3 + j;
#pragma unroll
            for (int k = 0; k < 33; k++) {
                if (k < kn) {
                    u64 w2 = pk2(__ldg(Wc + k * G3));
                    ulonglong2 x = xv[k];
                    fma2(gi01, x.x, w2); fma2(gi23, x.y, w2);
                }
            }
            reinterpret_cast<ulonglong2*>(sm->stGI)[half * G3 + j] = make_ulonglong2(gi01, gi23);
        }
        u64 gh01 = half ? 0ull : pk2(sm->bB[G3 + j]);
        u64 gh23 = gh01;
        mv_sm50(sm->sU + j, hsrc, half * 50, gh01, gh23);
        reinterpret_cast<ulonglong2*>(sm->stGH)[half * G3 + j] = make_ulonglong2(gh01, gh23);
    }
    __syncthreads();
    if (tid < HROW) {
        int idx = tid;
        float giz, gir, gin;
        if (HASX) {
            giz = sm->stGI[idx]            + sm->stGI[GROW + idx];
            gir = sm->stGI[HROW + idx]     + sm->stGI[GROW + HROW + idx];
            gin = sm->stGI[2 * HROW + idx] + sm->stGI[GROW + 2 * HROW + idx];
        } else {
            int i = idx >> 2;
            giz = sm->bB[i]; gir = sm->bB[HID + i]; gin = sm->bB[2 * HID + i];
        }
        float ghz = sm->stGH[idx]            + sm->stGH[GROW + idx];
        float ghr = sm->stGH[HROW + idx]     + sm->stGH[GROW + HROW + idx];
        float ghn = sm->stGH[2 * HROW + idx] + sm->stGH[GROW + 2 * HROW + idx];
        float z  = sigg(giz + ghz);
        float rr = sigg(gir + ghr);
        float n  = tanha(fmaf(rr, ghn, gin));
        float hnew = fmaf(z, hsrc[idx] - n, n);
        sm->hsB[idx] = hnew;
        if (gdict) gdict[idx] = hnew;
    }
    __syncthreads();
}

// ---- forward GRU step: gi weights from smem (sWx holds gruW), gh via preloaded __ldg(gruU) ----
__device__ __forceinline__ void fwd_step(const float* __restrict__ gruU,
                                         Smem* sm, const float* xg, int tid, int half, int j)
{
    if (tid < 600) {
        // gi: 32 iters, fully unrolled, 2x16 interleaved, weights in smem
        u64 gi01 = half ? 0ull : pk2(sm->bF[j]);
        u64 gi23 = gi01;
        {
            u64 c01 = 0, c23 = 0;
            const ulonglong2* xv = reinterpret_cast<const ulonglong2*>(xg) + 1 + half * 32;
            const float* Wc = sm->sWx + half * 32 * G3 + j;
#pragma unroll
            for (int k = 0; k < 16; k++) {
                u64 wa = pk2(Wc[k * G3]);
                u64 wb = pk2(Wc[(k + 16) * G3]);
                ulonglong2 xa = xv[k], xb = xv[k + 16];
                fma2(gi01, xa.x, wa); fma2(gi23, xa.y, wa);
                fma2(c01, xb.x, wb);  fma2(c23, xb.y, wb);
            }
            add2(gi01, c01); add2(gi23, c23);
        }
        // gh: 50 iters, preloaded-weight global matvec
        u64 gh01 = half ? 0ull : pk2(sm->bF[G3 + j]);
        u64 gh23 = gh01;
        mv_gl50(gruU + j, sm->hsF, half * 50, gh01, gh23);
        reinterpret_cast<ulonglong2*>(sm->stGI)[half * G3 + j] = make_ulonglong2(gi01, gi23);
        reinterpret_cast<ulonglong2*>(sm->stGH)[half * G3 + j] = make_ulonglong2(gh01, gh23);
    }
    __syncthreads();
    if (tid < HROW) {
        int idx = tid;
        float giz = sm->stGI[idx]            + sm->stGI[GROW + idx];
        float gir = sm->stGI[HROW + idx]     + sm->stGI[GROW + HROW + idx];
        float gin = sm->stGI[2 * HROW + idx] + sm->stGI[GROW + 2 * HROW + idx];
        float ghz = sm->stGH[idx]            + sm->stGH[GROW + idx];
        float ghr = sm->stGH[HROW + idx]     + sm->stGH[GROW + HROW + idx];
        float ghn = sm->stGH[2 * HROW + idx] + sm->stGH[GROW + 2 * HROW + idx];
        float z  = sigg(giz + ghz);
        float rr = sigg(gir + ghr);
        float n  = tanha(fmaf(rr, ghn, gin));
        float hnew = fmaf(z, sm->hsF[idx] - n, n);
        sm->hsF[idx] = hnew;
    }
    __syncthreads();
}

// ---- decoder event (R6 form) ----
__device__ __forceinline__ void decoder_event(int lvl,
                                              const float* __restrict__ decW,
                                              const float* __restrict__ decB,
                                              const float* __restrict__ meanW,
                                              const float* __restrict__ meanB,
                                              Smem* sm, const float* hbg,
                                              float* gout, int tid)
{
    float* stage = sm->stGI;
    if (tid < 500) {                  // [4,200]@[200,50], k in 10 groups of 20
        int j = tid % 50, kg = tid / 50;
        u64 a01 = 0, a23 = 0;
        const float* Wl = decW + lvl * 200 * 50;
        int kbeg = kg * 20;
#pragma unroll 5
        for (int kk = 0; kk < 20; kk++) {
            int k = kbeg + kk;
            const float* src = (k < HID) ? (sm->hsF + k * RPB) : (hbg + (k - HID) * RPB);
            ulonglong2 h = *reinterpret_cast<const ulonglong2*>(src);
            u64 w2 = pk2(__ldg(&Wl[k * 50 + j]));
            fma2(a01, h.x, w2); fma2(a23, h.y, w2);
        }
        reinterpret_cast<ulonglong2*>(stage)[tid] = make_ulonglong2(a01, a23);
    }
    __syncthreads();
    if (tid < 50) {
        float b = __ldg(&decB[lvl * 50 + tid]);
        float s0 = b, s1 = b, s2 = b, s3 = b;
#pragma unroll
        for (int g = 0; g < 10; g++) {
            int base = (g * 50 + tid) * 4;
            s0 += stage[base]; s1 += stage[base + 1]; s2 += stage[base + 2]; s3 += stage[base + 3];
        }
        sm->dec4[tid * 4 + 0] = fmaxf(s0, 0.f); sm->dec4[tid * 4 + 1] = fmaxf(s1, 0.f);
        sm->dec4[tid * 4 + 2] = fmaxf(s2, 0.f); sm->dec4[tid * 4 + 3] = fmaxf(s3, 0.f);
    }
    __syncthreads();
    {                                 // [4,50]@[50,64], k in 10 groups of 5
        int j = tid & 63, kg = tid >> 6;
        u64 m01 = 0, m23 = 0;
        const float* Ml = meanW + lvl * 50 * DDIM;
        int kbeg = kg * 5;
#pragma unroll
        for (int kk = 0; kk < 5; kk++) {
            int k = kbeg + kk;
            ulonglong2 d = reinterpret_cast<const ulonglong2*>(sm->dec4)[k];
            u64 w2 = pk2(__ldg(&Ml[k * DDIM + j]));
            fma2(m01, d.x, w2); fma2(m23, d.y, w2);
        }
        reinterpret_cast<ulonglong2*>(stage)[tid] = make_ulonglong2(m01, m23);
    }
    __syncthreads();
    if (tid < DDIM) {
        float b = __ldg(&meanB[lvl * DDIM + tid]);
        float s0 = b, s1 = b, s2 = b, s3 = b;
#pragma unroll
        for (int g = 0; g < 10; g++) {
            int base = (g * DDIM + tid) * 4;
            s0 += stage[base]; s1 += stage[base + 1]; s2 += stage[base + 2]; s3 += stage[base + 3];
        }
        gout[tid * RPB + 0] = s0; gout[tid * RPB + 1] = s1;
        gout[tid * RPB + 2] = s2; gout[tid * RPB + 3] = s3;
    }
    if (tid >= DDIM && tid < DDIM + RPB) gout[DDIM * RPB + (tid - DDIM)] = 1.0f;
    __syncthreads();
}

__global__ void __launch_bounds__(NT, 1)
naomi_kernel(const float* __restrict__ a,
             const float* __restrict__ gruW,  const float* __restrict__ gruU,
             const float* __restrict__ gruB,
             const float* __restrict__ bgruW, const float* __restrict__ bgruU,
             const float* __restrict__ bgruB,
             const float* __restrict__ decW,  const float* __restrict__ decB,
             const float* __restrict__ meanW, const float* __restrict__ meanB,
             float* __restrict__ out)
{
    extern __shared__ __align__(16) char smraw[];
    Smem* sm = reinterpret_cast<Smem*>(smraw);
    const int tid = threadIdx.x;
    const int bid = blockIdx.x;
    const int half = (tid < 600) ? (tid >= 300) : 0;
    const int j    = (tid < 600) ? (tid - half * 300) : 0;

    for (int i = tid; i < HID * G3; i += NT) sm->sU[i]  = bgruU[i];
    for (int i = tid; i < STC * G3; i += NT) sm->sWx[i] = bgruW[i];
    for (int i = tid; i < 2 * G3;   i += NT) { sm->bF[i] = gruB[i]; sm->bB[i] = bgruB[i]; }

    for (int t = tid; t < TLEN; t += NT) sm->obs[t] = (a[t * 3 + 2] > 0.5f) ? 1 : 0;

    float* gst = g_states + bid * TLEN * SROW;
    float* ghb = g_hback  + bid * (TLEN + 1) * HROW;
    float* ggi = g_gi     + (size_t)bid * TLEN * GROW;
    const int b0row = bid * RPB;
    for (int idx = tid; idx < RPB * STC * TLEN; idx += NT) {
        int t = idx & (TLEN - 1);
        int tmp = idx >> 8;
        int k = tmp % STC, r = tmp / STC;
        int b = b0row + r;
        float v = (k < DDIM) ? a[((b * DDIM + k) * TLEN + t) * 3]
                             : a[((b * DDIM) * TLEN + t) * 3 + 2];
        gst[t * SROW + k * RPB + r] = v;
    }
    for (int i = tid; i < HROW; i += NT) {
        sm->hsB[i] = 0.f; sm->hsF[i] = 0.f; ghb[TLEN * HROW + i] = 0.f;
    }
    __syncthreads();

    // ---- parallel prepass: gi[t] = states[t] @ bgru_W + b0, t = 1..255 (sWx = bgru_W) ----
    for (int task = tid; task < (TLEN - 1) * G3; task += NT) {
        int t = task / G3 + 1;
        int jj = task - (t - 1) * G3;
        u64 a01 = pk2(sm->bB[jj]), a23 = a01;
        const ulonglong2* xv = reinterpret_cast<const ulonglong2*>(gst + t * SROW);
#pragma unroll 5
        for (int k = 0; k < STC; k++) {
            u64 w2 = pk2(sm->sWx[k * G3 + jj]);
            ulonglong2 x = xv[k];
            fma2(a01, x.x, w2); fma2(a23, x.y, w2);
        }
        reinterpret_cast<ulonglong2*>(ggi)[(size_t)t * G3 + jj] = make_ulonglong2(a01, a23);
    }
    __syncthreads();

    // ---- swap: sWx region now holds gruW (fwd gi weights) ----
    for (int i = tid; i < DDIM * G3; i += NT) sm->sWx[i] = gruW[i];
    __syncthreads();

    // ---- phase 1: backward sweep ----
    for (int t = TLEN - 1; t >= 1; t--)
        sweep_step(sm, ggi + (size_t)t * GROW, ghb + t * HROW, tid, half, j);

    // ---- phase 2: forward interpolation ----
    fwd_step(gruU, sm, gst, tid, half, j);

    int curr_p = 0;
    while (curr_p < TLEN - 1) {
        if (sm->obs[curr_p + 1]) {
            curr_p++;
            fwd_step(gruU, sm, gst + curr_p * SROW, tid, half, j);
        } else {
            int next_p = curr_p + 1;
            while (next_p < TLEN && !sm->obs[next_p]) next_p++;
            int step = 1;
            while (curr_p + 2 * step <= next_p && step <= 8) step <<= 1;
            if (step > 1) step >>= 1;
            int lvl = (step == 8) ? 3 : (step == 4) ? 2 : (step == 2) ? 1 : 0;

            decoder_event(lvl, decW, decB, meanW, meanB, sm,
                          ghb + (curr_p + 2 * step) * HROW,
                          gst + (curr_p + step) * SROW, tid);

            if (step > 1) {
                int right = curr_p + step, left = curr_p + (step >> 1);
                back_step<true>(sm, bgruW, gst + right * SROW, ghb + (right + 1) * HROW,
                                ghb + right * HROW, tid, half, j);
                for (int i2 = right - 1; i2 >= left; i2--)
                    back_step<false>(sm, bgruW, nullptr, sm->hsB, ghb + i2 * HROW,
                                     tid, half, j);
            }
            sm->obs[curr_p + step] = 1;
            __syncthreads();
        }
    }

    // ---- output: out[b][d][t] = states[t][b][d+1] ----
    __syncthreads();
    for (int idx = tid; idx < RPB * DDIM * TLEN; idx += NT) {
        int t = idx & (TLEN - 1);
        int tmp = idx >> 8;
        int d = tmp % DDIM, r = tmp / DDIM;
        int b = b0row + r;
        out[(b * DDIM + d) * TLEN + t] = gst[t * SROW + (d + 1) * RPB + r];
    }
}

extern "C" void kernel_launch(void* const* d_in, const int* in_sizes, int n_in,
                              void* d_out, int out_size)
{
    const float* a     = (const float*)d_in[0];
    const float* gruW  = (const float*)d_in[1];
    const float* gruU  = (const float*)d_in[2];
    const float* gruB  = (const float*)d_in[3];
    const float* bgruW = (const float*)d_in[4];
    const float* bgruU = (const float*)d_in[5];
    const float* bgruB = (const float*)d_in[6];
    const float* decW  = (const float*)d_in[7];
    const float* decB  = (const float*)d_in[8];
    const float* meanW = (const float*)d_in[9];
    const float* meanB = (const float*)d_in[10];
    float* out = (float*)d_out;

    static int smem_set = 0;
    if (!smem_set) {
        cudaFuncSetAttribute(naomi_kernel, cudaFuncAttributeMaxDynamicSharedMemorySize,
                             (int)sizeof(Smem));
        smem_set = 1;
    }
    naomi_kernel<<<NBLK, NT, sizeof(Smem)>>>(a, gruW, gruU, gruB, bgruW, bgruU, bgruB,
                                             decW, decB, meanW, meanB, out);
}

// round 16
// speedup vs baseline: 1.5407x; 1.0272x over previous
#include <cuda_runtime.h>

#define DDIM  64
#define TLEN  256
#define HID   100
#define G3    300
#define NBLK  128
#define RPB   4
#define NT    608
#define STC   65
#define SROW  (STC*RPB)   // 260
#define HROW  (HID*RPB)   // 400
#define GROW  (G3*RPB)    // 1200

typedef unsigned long long u64;

__device__ __align__(16) float g_states[NBLK * TLEN * SROW];
__device__ __align__(16) float g_hback [NBLK * (TLEN + 1) * HROW];
__device__ __align__(16) float g_gi    [(size_t)NBLK * TLEN * GROW];
__device__ __align__(16) float g_fgi   [(size_t)NBLK * TLEN * GROW];

struct __align__(16) Smem {
    float sGU[HID * G3];    // gru_U  (120000 B) — fwd gh weights
    float sWx[STC * G3];    // bgru_W during prepass; gruW after swap (78000 B)
    float stGI[2 * GROW];   // partial slots ( 9600 B)
    float stGH[2 * GROW];   // partial slots ( 9600 B)
    float hsF[HROW];
    float hsB[HROW];
    float dec4[50 * RPB];
    float bF[2 * G3];
    float bB[2 * G3];
    int   obs[TLEN];
};  // ~227 KB

__device__ __forceinline__ float tanha(float x) {
    float y; asm("tanh.approx.f32 %0, %1;" : "=f"(y) : "f"(x)); return y;
}
__device__ __forceinline__ u64 pk2(float w) {
    unsigned wi = __float_as_uint(w);
    u64 r; asm("mov.b64 %0, {%1, %1};" : "=l"(r) : "r"(wi), "r"(wi)); return r;
}
__device__ __forceinline__ void fma2(u64& a, u64 v, u64 w) {
    asm("fma.rn.f32x2 %0, %1, %2, %0;" : "+l"(a) : "l"(v), "l"(w));
}
__device__ __forceinline__ void add2(u64& a, u64 b) {
    asm("add.rn.f32x2 %0, %0, %1;" : "+l"(a) : "l"(b));
}
__device__ __forceinline__ float sigg(float x) { return fmaf(0.5f, tanha(0.5f * x), 0.5f); }

// 50-iter smem-weight matvec, fully unrolled, 2x25 chains
__device__ __forceinline__ void mv_sm50(const float* __restrict__ Wcol, const float* hv_,
                                        int kb, u64& a01, u64& a23)
{
    const ulonglong2* hv = reinterpret_cast<const ulonglong2*>(hv_) + kb;
    const float* Wc = Wcol + kb * G3;
    u64 b01 = 0, b23 = 0;
#pragma unroll
    for (int k = 0; k < 25; k++) {
        u64 wa = pk2(Wc[k * G3]);
        u64 wb = pk2(Wc[(k + 25) * G3]);
        ulonglong2 ha = hv[k], hb = hv[k + 25];
        fma2(a01, ha.x, wa); fma2(a23, ha.y, wa);
        fma2(b01, hb.x, wb); fma2(b23, hb.y, wb);
    }
    add2(a01, b01); add2(a23, b23);
}

// 50-iter register-weight matvec (weights pinned in ureg), 2x25 chains
__device__ __forceinline__ void mv_reg50(const float (&ureg)[50], const float* hv_,
                                         int kb, u64& a01, u64& a23)
{
    const ulonglong2* hv = reinterpret_cast<const ulonglong2*>(hv_) + kb;
    u64 b01 = 0, b23 = 0;
#pragma unroll
    for (int k = 0; k < 25; k++) {
        u64 wa = pk2(ureg[k]);
        u64 wb = pk2(ureg[k + 25]);
        ulonglong2 ha = hv[k], hb = hv[k + 25];
        fma2(a01, ha.x, wa); fma2(a23, ha.y, wa);
        fma2(b01, hb.x, wb); fma2(b23, hb.y, wb);
    }
    add2(a01, b01); add2(a23, b23);
}

// ---- sweep step: gi prefetched from g_gi; gh via register weights ----
__device__ __forceinline__ void sweep_step(Smem* sm, const float (&ureg)[50],
                                           const float* __restrict__ gv,
                                           float* gdict, int tid, int half, int j)
{
    float pgz = 0.f, pgr = 0.f, pgn = 0.f;
    if (tid < HROW) {
        pgz = __ldg(gv + tid); pgr = __ldg(gv + HROW + tid); pgn = __ldg(gv + 2 * HROW + tid);
    }
    if (tid < 600) {
        u64 a01 = half ? 0ull : pk2(sm->bB[G3 + j]), a23 = a01;
        mv_reg50(ureg, sm->hsB, half * 50, a01, a23);
        reinterpret_cast<ulonglong2*>(sm->stGH)[half * G3 + j] = make_ulonglong2(a01, a23);
    }
    __syncthreads();
    if (tid < HROW) {
        int idx = tid;
        float ghz = sm->stGH[idx]            + sm->stGH[GROW + idx];
        float ghr = sm->stGH[HROW + idx]     + sm->stGH[GROW + HROW + idx];
        float ghn = sm->stGH[2 * HROW + idx] + sm->stGH[GROW + 2 * HROW + idx];
        float z  = sigg(pgz + ghz);
        float rr = sigg(pgr + ghr);
        float n  = tanha(fmaf(rr, ghn, pgn));
        float hnew = fmaf(z, sm->hsB[idx] - n, n);
        sm->hsB[idx] = hnew; gdict[idx] = hnew;
    }
    __syncthreads();
}

// ---- forward GRU step: gi prefetched from g_fgi; gh from smem gru_U ----
__device__ __forceinline__ void fwd_step(Smem* sm, const float* __restrict__ gv,
                                         int tid, int half, int j)
{
    float pgz = 0.f, pgr = 0.f, pgn = 0.f;
    if (tid < HROW) {
        pgz = gv[tid]; pgr = gv[HROW + tid]; pgn = gv[2 * HROW + tid];
    }
    if (tid < 600) {
        u64 a01 = half ? 0ull : pk2(sm->bF[G3 + j]), a23 = a01;
        mv_sm50(sm->sGU + j, sm->hsF, half * 50, a01, a23);
        reinterpret_cast<ulonglong2*>(sm->stGH)[half * G3 + j] = make_ulonglong2(a01, a23);
    }
    __syncthreads();
    if (tid < HROW) {
        int idx = tid;
        float ghz = sm->stGH[idx]            + sm->stGH[GROW + idx];
        float ghr = sm->stGH[HROW + idx]     + sm->stGH[GROW + HROW + idx];
        float ghn = sm->stGH[2 * HROW + idx] + sm->stGH[GROW + 2 * HROW + idx];
        float z  = sigg(pgz + ghz);
        float rr = sigg(pgr + ghr);
        float n  = tanha(fmaf(rr, ghn, pgn));
        float hnew = fmaf(z, sm->hsF[idx] - n, n);
        sm->hsF[idx] = hnew;
    }
    __syncthreads();
}

// ---- backward GRU step (recompute): x-weights via __ldg(bgruW), gh via reg weights ----
template<bool HASX>
__device__ __forceinline__ void back_step(Smem* sm, const float (&ureg)[50],
                                          const float* __restrict__ bgruW,
                                          const float* __restrict__ xg, const float* hsrc,
                                          float* gdict, int tid, int half, int j)
{
    if (tid < 600) {
        if (HASX) {
            int kb = half ? 33 : 0;
            const int kn = half ? 32 : 33;
            u64 gi01 = half ? 0ull : pk2(sm->bB[j]);
            u64 gi23 = gi01;
            const ulonglong2* xv = reinterpret_cast<const ulonglong2*>(xg) + kb;
            const float* Wc = bgruW + kb * G3 + j;
#pragma unroll
            for (int k = 0; k < 33; k++) {
                if (k < kn) {
                    u64 w2 = pk2(__ldg(Wc + k * G3));
                    ulonglong2 x = xv[k];
                    fma2(gi01, x.x, w2); fma2(gi23, x.y, w2);
                }
            }
            reinterpret_cast<ulonglong2*>(sm->stGI)[half * G3 + j] = make_ulonglong2(gi01, gi23);
        }
        u64 gh01 = half ? 0ull : pk2(sm->bB[G3 + j]);
        u64 gh23 = gh01;
        mv_reg50(ureg, hsrc, half * 50, gh01, gh23);
        reinterpret_cast<ulonglong2*>(sm->stGH)[half * G3 + j] = make_ulonglong2(gh01, gh23);
    }
    __syncthreads();
    if (tid < HROW) {
        int idx = tid;
        float giz, gir, gin;
        if (HASX) {
            giz = sm->stGI[idx]            + sm->stGI[GROW + idx];
            gir = sm->stGI[HROW + idx]     + sm->stGI[GROW + HROW + idx];
            gin = sm->stGI[2 * HROW + idx] + sm->stGI[GROW + 2 * HROW + idx];
        } else {
            int i = idx >> 2;
            giz = sm->bB[i]; gir = sm->bB[HID + i]; gin = sm->bB[2 * HID + i];
        }
        float ghz = sm->stGH[idx]            + sm->stGH[GROW + idx];
        float ghr = sm->stGH[HROW + idx]     + sm->stGH[GROW + HROW + idx];
        float ghn = sm->stGH[2 * HROW + idx] + sm->stGH[GROW + 2 * HROW + idx];
        float z  = sigg(giz + ghz);
        float rr = sigg(gir + ghr);
        float n  = tanha(fmaf(rr, ghn, gin));
        float hnew = fmaf(z, hsrc[idx] - n, n);
        sm->hsB[idx] = hnew;
        if (gdict) gdict[idx] = hnew;
    }
    __syncthreads();
}

// ---- decoder event; tail computes fwd-gi of the new state into g_fgi ----
__device__ __forceinline__ void decoder_event(int lvl,
                                              const float* __restrict__ decW,
                                              const float* __restrict__ decB,
                                              const float* __restrict__ meanW,
                                              const float* __restrict__ meanB,
                                              Smem* sm, const float* hbg,
                                              float* gout, float* fgiRow, int tid)
{
    float* stage = sm->stGI;
    if (tid < 500) {                  // [4,200]@[200,50], k in 10 groups of 20
        int j = tid % 50, kg = tid / 50;
        u64 a01 = 0, a23 = 0;
        const float* Wl = decW + lvl * 200 * 50;
        int kbeg = kg * 20;
#pragma unroll 5
        for (int kk = 0; kk < 20; kk++) {
            int k = kbeg + kk;
            const float* src = (k < HID) ? (sm->hsF + k * RPB) : (hbg + (k - HID) * RPB);
            ulonglong2 h = *reinterpret_cast<const ulonglong2*>(src);
            u64 w2 = pk2(__ldg(&Wl[k * 50 + j]));
            fma2(a01, h.x, w2); fma2(a23, h.y, w2);
        }
        reinterpret_cast<ulonglong2*>(stage)[tid] = make_ulonglong2(a01, a23);
    }
    __syncthreads();
    if (tid < 50) {
        float b = __ldg(&decB[lvl * 50 + tid]);
        float s0 = b, s1 = b, s2 = b, s3 = b;
#pragma unroll
        for (int g = 0; g < 10; g++) {
            int base = (g * 50 + tid) * 4;
            s0 += stage[base]; s1 += stage[base + 1]; s2 += stage[base + 2]; s3 += stage[base + 3];
        }
        sm->dec4[tid * 4 + 0] = fmaxf(s0, 0.f); sm->dec4[tid * 4 + 1] = fmaxf(s1, 0.f);
        sm->dec4[tid * 4 + 2] = fmaxf(s2, 0.f); sm->dec4[tid * 4 + 3] = fmaxf(s3, 0.f);
    }
    __syncthreads();
    if (tid < 320) {                  // [4,50]@[50,64], k in 5 groups of 10 (FIX: full coverage at NT=608)
        int j = tid & 63, kg = tid >> 6;   // kg 0..4
        u64 m01 = 0, m23 = 0;
        const float* Ml = meanW + lvl * 50 * DDIM;
        int kbeg = kg * 10;
#pragma unroll
        for (int kk = 0; kk < 10; kk++) {
            int k = kbeg + kk;
            ulonglong2 d = reinterpret_cast<const ulonglong2*>(sm->dec4)[k];
            u64 w2 = pk2(__ldg(&Ml[k * DDIM + j]));
            fma2(m01, d.x, w2); fma2(m23, d.y, w2);
        }
        reinterpret_cast<ulonglong2*>(stage)[tid] = make_ulonglong2(m01, m23);
    }
    __syncthreads();
    if (tid < DDIM) {
        float b = __ldg(&meanB[lvl * DDIM + tid]);
        float s0 = b, s1 = b, s2 = b, s3 = b;
#pragma unroll
        for (int g = 0; g < 5; g++) {
            int base = (g * DDIM + tid) * 4;
            s0 += stage[base]; s1 += stage[base + 1]; s2 += stage[base + 2]; s3 += stage[base + 3];
        }
        gout[tid * RPB + 0] = s0; gout[tid * RPB + 1] = s1;
        gout[tid * RPB + 2] = s2; gout[tid * RPB + 3] = s3;
    }
    if (tid >= DDIM && tid < DDIM + RPB) gout[DDIM * RPB + (tid - DDIM)] = 1.0f;
    __syncthreads();
    // fwd-gi of the new state (full-k per column; sWx holds gruW)
    if (tid < G3) {
        u64 a01 = pk2(sm->bF[tid]), a23 = a01;
        u64 b01 = 0, b23 = 0;
        const ulonglong2* xv = reinterpret_cast<const ulonglong2*>(gout) + 1;
        const float* Wc = sm->sWx + tid;
#pragma unroll
        for (int k = 0; k < 32; k++) {
            u64 wa = pk2(Wc[k * G3]);
            u64 wb = pk2(Wc[(k + 32) * G3]);
            ulonglong2 xa = xv[k], xb = xv[k + 32];
            fma2(a01, xa.x, wa); fma2(a23, xa.y, wa);
            fma2(b01, xb.x, wb); fma2(b23, xb.y, wb);
        }
        add2(a01, b01); add2(a23, b23);
        reinterpret_cast<ulonglong2*>(fgiRow)[tid] = make_ulonglong2(a01, a23);
    }
    __syncthreads();
}

__global__ void __launch_bounds__(NT, 1)
naomi_kernel(const float* __restrict__ a,
             const float* __restrict__ gruW,  const float* __restrict__ gruU,
             const float* __restrict__ gruB,
             const float* __restrict__ bgruW, const float* __restrict__ bgruU,
             const float* __restrict__ bgruB,
             const float* __restrict__ decW,  const float* __restrict__ decB,
             const float* __restrict__ meanW, const float* __restrict__ meanB,
             float* __restrict__ out)
{
    extern __shared__ __align__(16) char smraw[];
    Smem* sm = reinterpret_cast<Smem*>(smraw);
    const int tid = threadIdx.x;
    const int bid = blockIdx.x;
    const int half = (tid < 600) ? (tid >= 300) : 0;
    const int j    = (tid < 600) ? (tid - half * 300) : 0;

    for (int i = tid; i < HID * G3; i += NT) sm->sGU[i] = gruU[i];
    for (int i = tid; i < STC * G3; i += NT) sm->sWx[i] = bgruW[i];
    for (int i = tid; i < 2 * G3;   i += NT) { sm->bF[i] = gruB[i]; sm->bB[i] = bgruB[i]; }

    for (int t = tid; t < TLEN; t += NT) sm->obs[t] = (a[t * 3 + 2] > 0.5f) ? 1 : 0;

    float* gst = g_states + bid * TLEN * SROW;
    float* ghb = g_hback  + bid * (TLEN + 1) * HROW;
    float* ggi = g_gi     + (size_t)bid * TLEN * GROW;
    float* gfg = g_fgi    + (size_t)bid * TLEN * GROW;
    const int b0row = bid * RPB;
    for (int idx = tid; idx < RPB * STC * TLEN; idx += NT) {
        int t = idx & (TLEN - 1);
        int tmp = idx >> 8;
        int k = tmp % STC, r = tmp / STC;
        int b = b0row + r;
        float v = (k < DDIM) ? a[((b * DDIM + k) * TLEN + t) * 3]
                             : a[((b * DDIM) * TLEN + t) * 3 + 2];
        gst[t * SROW + k * RPB + r] = v;
    }
    for (int i = tid; i < HROW; i += NT) {
        sm->hsB[i] = 0.f; sm->hsF[i] = 0.f; ghb[TLEN * HROW + i] = 0.f;
    }
    __syncthreads();

    // ---- prepass A: backward gi[t] = states[t] @ bgru_W + b0, t = 1..255 ----
    for (int task = tid; task < (TLEN - 1) * G3; task += NT) {
        int t = task / G3 + 1;
        int jj = task - (t - 1) * G3;
        u64 a01 = pk2(sm->bB[jj]), a23 = a01;
        const ulonglong2* xv = reinterpret_cast<const ulonglong2*>(gst + t * SROW);
#pragma unroll 5
        for (int k = 0; k < STC; k++) {
            u64 w2 = pk2(sm->sWx[k * G3 + jj]);
            ulonglong2 x = xv[k];
            fma2(a01, x.x, w2); fma2(a23, x.y, w2);
        }
        reinterpret_cast<ulonglong2*>(ggi)[(size_t)t * G3 + jj] = make_ulonglong2(a01, a23);
    }
    __syncthreads();

    // ---- swap: sWx now holds gruW ----
    for (int i = tid; i < DDIM * G3; i += NT) sm->sWx[i] = gruW[i];
    __syncthreads();

    // ---- prepass B: fwd gi for observed t ----
    for (int task = tid; task < TLEN * G3; task += NT) {
        int t = task / G3;
        int jj = task - t * G3;
        if (sm->obs[t]) {
            u64 a01 = pk2(sm->bF[jj]), a23 = a01;
            const ulonglong2* xv = reinterpret_cast<const ulonglong2*>(gst + t * SROW) + 1;
#pragma unroll 4
            for (int k = 0; k < DDIM; k++) {
                u64 w2 = pk2(sm->sWx[k * G3 + jj]);
                ulonglong2 x = xv[k];
                fma2(a01, x.x, w2); fma2(a23, x.y, w2);
            }
            reinterpret_cast<ulonglong2*>(gfg)[(size_t)t * G3 + jj] = make_ulonglong2(a01, a23);
        }
    }
    __syncthreads();

    // ---- bgru_U columns into registers ----
    float ureg[50];
#pragma unroll
    for (int k = 0; k < 50; k++)
        ureg[k] = (tid < 600) ? __ldg(&bgruU[(half * 50 + k) * G3 + j]) : 0.0f;

    // ---- phase 1: backward sweep ----
    for (int t = TLEN - 1; t >= 1; t--)
        sweep_step(sm, ureg, ggi + (size_t)t * GROW, ghb + t * HROW, tid, half, j);

    // ---- phase 2: forward interpolation ----
    fwd_step(sm, gfg, tid, half, j);

    int curr_p = 0;
    while (curr_p < TLEN - 1) {
        if (sm->obs[curr_p + 1]) {
            curr_p++;
            fwd_step(sm, gfg + (size_t)curr_p * GROW, tid, half, j);
        } else {
            int next_p = curr_p + 1;
            while (next_p < TLEN && !sm->obs[next_p]) next_p++;
            int step = 1;
            while (curr_p + 2 * step <= next_p && step <= 8) step <<= 1;
            if (step > 1) step >>= 1;
            int lvl = (step == 8) ? 3 : (step == 4) ? 2 : (step == 2) ? 1 : 0;

            decoder_event(lvl, decW, decB, meanW, meanB, sm,
                          ghb + (curr_p + 2 * step) * HROW,
                          gst + (curr_p + step) * SROW,
                          gfg + (size_t)(curr_p + step) * GROW, tid);

            if (step > 1) {
                int right = curr_p + step, left = curr_p + (step >> 1);
                back_step<true>(sm, ureg, bgruW, gst + right * SROW, ghb + (right + 1) * HROW,
                                ghb + right * HROW, tid, half, j);
                for (int i2 = right - 1; i2 >= left; i2--)
                    back_step<false>(sm, ureg, bgruW, nullptr, sm->hsB, ghb + i2 * HROW,
                                     tid, half, j);
            }
            sm->obs[curr_p + step] = 1;
            __syncthreads();
        }
    }

    // ---- output: out[b][d][t] = states[t][b][d+1] ----
    __syncthreads();
    for (int idx = tid; idx < RPB * DDIM * TLEN; idx += NT) {
        int t = idx & (TLEN - 1);
        int tmp = idx >> 8;
        int d = tmp % DDIM, r = tmp / DDIM;
        int b = b0row + r;
        out[(b * DDIM + d) * TLEN + t] = gst[t * SROW + (d + 1) * RPB + r];
    }
}

extern "C" void kernel_launch(void* const* d_in, const int* in_sizes, int n_in,
                              void* d_out, int out_size)
{
    const float* a     = (const float*)d_in[0];
    const float* gruW  = (const float*)d_in[1];
    const float* gruU  = (const float*)d_in[2];
    const float* gruB  = (const float*)d_in[3];
    const float* bgruW = (const float*)d_in[4];
    const float* bgruU = (const float*)d_in[5];
    const float* bgruB = (const float*)d_in[6];
    const float* decW  = (const float*)d_in[7];
    const float* decB  = (const float*)d_in[8];
    const float* meanW = (const float*)d_in[9];
    const float* meanB = (const float*)d_in[10];
    float* out = (float*)d_out;

    static int smem_set = 0;
    if (!smem_set) {
        cudaFuncSetAttribute(naomi_kernel, cudaFuncAttributeMaxDynamicSharedMemorySize,
                             (int)sizeof(Smem));
        smem_set = 1;
    }
    naomi_kernel<<<NBLK, NT, sizeof(Smem)>>>(a, gruW, gruU, gruB, bgruW, bgruU, bgruB,
                                             decW, decB, meanW, meanB, out);
}